// round 8
// baseline (speedup 1.0000x reference)
#include <cuda_runtime.h>
#include <cstdint>

#define BB 16
#define NN 2048
#define HH 128
#define KNN 16
#define NSPLIT 4
#define SPLEN (NN / NSPLIT)   // 512

// ---------------- scratch (device globals; no allocs allowed) ----------------
__device__ int   g_nbr[BB * NN * KNN];              // final neighbor indices (batch-local)
__device__ float g_cd[BB * NN * NSPLIT * KNN];      // split candidates: distances
__device__ int   g_ci[BB * NN * NSPLIT * KNN];      // split candidates: indices
__device__ float g_h1[BB * NN * HH];
__device__ float g_h2[BB * NN * HH];
__device__ float g_WT[4 * HH * HH];                 // W2r^T, W2s^T, W3r^T, W3s^T (k-major)

// ---------------- kNN phase 1: split-K brute force --------------------------
// grid (16 slices, 4 splits, 16 batches), block 128. One thread = one query,
// scanning a 512-candidate slice held in 8KB smem.
__global__ __launch_bounds__(128) void knn_split_kernel(const float* __restrict__ pts) {
    __shared__ float4 sp[SPLEN];   // (x, y, z, |p|^2) : 8KB
    const int b = blockIdx.z;
    const int j0 = blockIdx.y * SPLEN;
    const float* pb = pts + (size_t)b * NN * 3;

    for (int t = threadIdx.x; t < SPLEN; t += 128) {
        const int j = j0 + t;
        float x = pb[j * 3], y = pb[j * 3 + 1], z = pb[j * 3 + 2];
        sp[t] = make_float4(x, y, z, x * x + y * y + z * z);
    }
    __syncthreads();

    const int i = blockIdx.x * 128 + threadIdx.x;
    const float px = pb[i * 3], py = pb[i * 3 + 1], pz = pb[i * 3 + 2];
    const float pw = px * px + py * py + pz * pz;

    float bd[KNN];
    int   bi[KNN];
#pragma unroll
    for (int s = 0; s < KNN; s++) { bd[s] = 3.4e38f; bi[s] = 0; }
    float wv = 3.4e38f;

#pragma unroll 2
    for (int t = 0; t < SPLEN; t++) {
        float4 q = sp[t];
        float dot = px * q.x + py * q.y + pz * q.z;
        float d2 = pw + q.w - 2.0f * dot;
        if (d2 < wv) {
            bool done = false;
#pragma unroll
            for (int s = 0; s < KNN; s++) {
                if (!done && bd[s] == wv) { bd[s] = d2; bi[s] = j0 + t; done = true; }
            }
            wv = bd[0];
#pragma unroll
            for (int s = 1; s < KNN; s++) wv = fmaxf(wv, bd[s]);
        }
    }

    const size_t o = (((size_t)b * NN + i) * NSPLIT + blockIdx.y) * KNN;
#pragma unroll
    for (int s = 0; s < KNN; s++) { g_cd[o + s] = bd[s]; g_ci[o + s] = bi[s]; }
}

// ---------------- kNN phase 2: merge 64 -> 16 per query ---------------------
// grid 128, block 256. One thread per query.
__global__ __launch_bounds__(256) void knn_merge_kernel() {
    const int q = blockIdx.x * 256 + threadIdx.x;   // 0..32767
    const float* cd = g_cd + (size_t)q * (NSPLIT * KNN);
    const int*   ci = g_ci + (size_t)q * (NSPLIT * KNN);

    float bd[KNN];
    int   bi[KNN];
#pragma unroll
    for (int s = 0; s < KNN; s++) { bd[s] = 3.4e38f; bi[s] = 0; }
    float wv = 3.4e38f;

    for (int t = 0; t < NSPLIT * KNN; t++) {
        float d2 = cd[t];
        if (d2 < wv) {
            int j = ci[t];
            bool done = false;
#pragma unroll
            for (int s = 0; s < KNN; s++) {
                if (!done && bd[s] == wv) { bd[s] = d2; bi[s] = j; done = true; }
            }
            wv = bd[0];
#pragma unroll
            for (int s = 1; s < KNN; s++) wv = fmaxf(wv, bd[s]);
        }
    }

    int* o = g_nbr + (size_t)q * KNN;
#pragma unroll
    for (int s = 0; s < KNN; s++) o[s] = bi[s];
}

// ---------------- layer 1 (input dim 3): 1 thread per point ------------------
// grid 128, block 256.
__global__ __launch_bounds__(256) void layer1_kernel(const float* __restrict__ pts,
                                                     const float* __restrict__ W1r,
                                                     const float* __restrict__ b1,
                                                     const float* __restrict__ W1s) {
    __shared__ float sWr[HH * 3], sWs[HH * 3], sb[HH];
    const int tid = threadIdx.x;
    for (int t = tid; t < HH * 3; t += 256) { sWr[t] = W1r[t]; sWs[t] = W1s[t]; }
    if (tid < 128) sb[tid] = b1[tid];
    __syncthreads();

    const int i = blockIdx.x * 256 + tid;
    const int base = (i >> 11) << 11;

    const float* xp = pts + (size_t)i * 3;
    const float x0 = xp[0], x1 = xp[1], x2 = xp[2];

    float a0 = 0.f, a1 = 0.f, a2 = 0.f;
    const int* nb = g_nbr + (size_t)i * KNN;
#pragma unroll
    for (int n = 0; n < KNN; n++) {
        int j = nb[n];
        const float* c = pts + (size_t)(base + j) * 3;
        a0 += c[0]; a1 += c[1]; a2 += c[2];
    }

    float* orow = g_h1 + (size_t)i * HH;
#pragma unroll 2
    for (int h = 0; h < HH; h += 4) {
        float4 v;
        float* vv = (float*)&v;
#pragma unroll
        for (int e = 0; e < 4; e++) {
            int hh = h + e;
            float s = sb[hh]
                    + sWr[hh * 3 + 0] * a0 + sWr[hh * 3 + 1] * a1 + sWr[hh * 3 + 2] * a2
                    + sWs[hh * 3 + 0] * x0 + sWs[hh * 3 + 1] * x1 + sWs[hh * 3 + 2] * x2;
            vv[e] = fmaxf(s, 0.0f);
        }
        *(float4*)(orow + h) = v;
    }
}

// ---------------- W transpose (k-major for coalesced GEMM staging) -----------
// grid (64, 4), block 256
__global__ __launch_bounds__(256) void transpose_kernel(const float* __restrict__ W2r,
                                                        const float* __restrict__ W2s,
                                                        const float* __restrict__ W3r,
                                                        const float* __restrict__ W3s) {
    const float* src[4] = {W2r, W2s, W3r, W3s};
    int m = blockIdx.y;
    int idx = blockIdx.x * 256 + threadIdx.x;   // 0..16383
    int k = idx >> 7, h = idx & 127;
    g_WT[m * HH * HH + k * HH + h] = src[m][h * HH + k];
}

// ---------------- layers 2/3: gather + dual GEMM (scalar FFMA, R6 exact) -----
// grid 512, block 256, 64 points per block. dyn smem 83968 B.
#define APITCH 132

template <bool RELU>
__global__ __launch_bounds__(256) void layer_kernel(const float* __restrict__ xin,
                                                    const float* __restrict__ WrT,
                                                    const float* __restrict__ bvec,
                                                    const float* __restrict__ WsT,
                                                    float* __restrict__ xout) {
    extern __shared__ float smf[];
    float* As   = smf;                       // [64][APITCH] neighbor-sum
    float* Xs   = smf + 64 * APITCH;         // [64][APITCH] self features
    float* Wr_s = smf + 2 * 64 * APITCH;     // [16][128]
    float* Ws_s = Wr_s + 16 * HH;            // [16][128]

    const int tid = threadIdx.x;
    const int P0 = blockIdx.x * 64;
    const int base = (P0 >> 11) << 11;

    // ---- gather phase: 4 threads per point, each owns 32 dims ----
    {
        const int p = tid >> 2, c = tid & 3;
        const float4* xr = (const float4*)(xin + ((size_t)P0 + p) * HH + c * 32);
        float4 acc[8];
#pragma unroll
        for (int q = 0; q < 8; q++) {
            float4 v = xr[q];
            *(float4*)(Xs + p * APITCH + c * 32 + q * 4) = v;
            acc[q] = make_float4(0.f, 0.f, 0.f, 0.f);
        }
        const int* nb = g_nbr + ((size_t)P0 + p) * KNN;
        for (int n = 0; n < KNN; n++) {
            int j = nb[n];
            const float4* ar = (const float4*)(xin + ((size_t)base + j) * HH + c * 32);
#pragma unroll
            for (int q = 0; q < 8; q++) {
                float4 v = ar[q];
                acc[q].x += v.x; acc[q].y += v.y; acc[q].z += v.z; acc[q].w += v.w;
            }
        }
#pragma unroll
        for (int q = 0; q < 8; q++)
            *(float4*)(As + p * APITCH + c * 32 + q * 4) = acc[q];
    }

    // ---- GEMM phase: warp owns 8 rows (m), lane owns 4 cols (h) ----
    const int warp = tid >> 5, lane = tid & 31;
    const int m0 = warp * 8, h0 = lane * 4;

    float acc[8][4];
#pragma unroll
    for (int i = 0; i < 8; i++)
#pragma unroll
        for (int j = 0; j < 4; j++) acc[i][j] = 0.f;

    for (int k0 = 0; k0 < HH; k0 += 16) {
        __syncthreads();   // also covers gather -> first compute
        {
            const float4* s1 = (const float4*)(WrT + (size_t)k0 * HH);
            const float4* s2 = (const float4*)(WsT + (size_t)k0 * HH);
            ((float4*)Wr_s)[tid] = s1[tid]; ((float4*)Wr_s)[tid + 256] = s1[tid + 256];
            ((float4*)Ws_s)[tid] = s2[tid]; ((float4*)Ws_s)[tid + 256] = s2[tid + 256];
        }
        __syncthreads();
#pragma unroll
        for (int kk = 0; kk < 16; kk++) {
            const int k = k0 + kk;
            float a[8], x[8];
#pragma unroll
            for (int i = 0; i < 8; i++) {
                a[i] = As[(m0 + i) * APITCH + k];   // broadcast across lanes
                x[i] = Xs[(m0 + i) * APITCH + k];
            }
            float4 wr = *(const float4*)(Wr_s + kk * HH + h0);
            float4 ws = *(const float4*)(Ws_s + kk * HH + h0);
            const float* wrf = (const float*)&wr;
            const float* wsf = (const float*)&ws;
#pragma unroll
            for (int i = 0; i < 8; i++)
#pragma unroll
                for (int j = 0; j < 4; j++)
                    acc[i][j] += a[i] * wrf[j] + x[i] * wsf[j];
        }
    }

    // ---- epilogue: + bias, optional relu, vectorized row stores ----
    const float4 bv = *(const float4*)(bvec + h0);
    const float* bf = (const float*)&bv;
#pragma unroll
    for (int i = 0; i < 8; i++) {
        float4 o; float* of = (float*)&o;
#pragma unroll
        for (int j = 0; j < 4; j++) {
            float v = acc[i][j] + bf[j];
            if (RELU) v = fmaxf(v, 0.0f);
            of[j] = v;
        }
        *(float4*)(xout + ((size_t)P0 + m0 + i) * HH + h0) = o;
    }
}

// ---------------- launch: bind inputs BY SIZE (order-robust) ----------------
extern "C" void kernel_launch(void* const* d_in, const int* in_sizes, int n_in,
                              void* d_out, int out_size) {
    const float* pts = nullptr;
    const float* w3[2]  = {nullptr, nullptr};           int n3 = 0;
    const float* wH[4]  = {nullptr, nullptr, nullptr, nullptr}; int nH = 0;
    const float* bs[3]  = {nullptr, nullptr, nullptr};  int nb_ = 0;
    for (int i = 0; i < n_in; i++) {
        const int sz = in_sizes[i];
        const float* p = (const float*)d_in[i];
        if (sz == BB * NN * 3)      pts = p;
        else if (sz == HH * 3)      { if (n3 < 2) w3[n3++] = p; }
        else if (sz == HH * HH)     { if (nH < 4) wH[nH++] = p; }
        else if (sz == HH)          { if (nb_ < 3) bs[nb_++] = p; }
    }
    const float* W1r = w3[0];  const float* W1s = w3[1];
    const float* W2r = wH[0];  const float* W2s = wH[1];
    const float* W3r = wH[2];  const float* W3s = wH[3];
    const float* b1  = bs[0];  const float* b2  = bs[1];  const float* b3 = bs[2];
    float* out = (float*)d_out;

    const int SMEM = (2 * 64 * APITCH + 2 * 16 * HH) * (int)sizeof(float);  // 83968
    cudaFuncSetAttribute(layer_kernel<true>,  cudaFuncAttributeMaxDynamicSharedMemorySize, SMEM);
    cudaFuncSetAttribute(layer_kernel<false>, cudaFuncAttributeMaxDynamicSharedMemorySize, SMEM);

    float *h1, *h2, *wt;
    cudaGetSymbolAddress((void**)&h1, g_h1);
    cudaGetSymbolAddress((void**)&h2, g_h2);
    cudaGetSymbolAddress((void**)&wt, g_WT);

    transpose_kernel<<<dim3(64, 4), 256>>>(W2r, W2s, W3r, W3s);
    knn_split_kernel<<<dim3(16, NSPLIT, 16), 128>>>(pts);
    knn_merge_kernel<<<128, 256>>>();
    layer1_kernel<<<128, 256>>>(pts, W1r, b1, W1s);
    layer_kernel<true><<<512, 256, SMEM>>>(h1, wt, b2, wt + HH * HH, h2);
    layer_kernel<false><<<512, 256, SMEM>>>(h2, wt + 2 * HH * HH, b3, wt + 3 * HH * HH, out);
}

// round 9
// speedup vs baseline: 1.6492x; 1.6492x over previous
#include <cuda_runtime.h>
#include <cstdint>

#define BB 16
#define NN 2048
#define HH 128
#define KNN 16

// ---------------- scratch (device globals; no allocs allowed) ----------------
__device__ int   g_nbr[BB * NN * KNN];      // neighbor indices (batch-local)
__device__ float g_h1[BB * NN * HH];
__device__ float g_h2[BB * NN * HH];
__device__ float g_WT[4 * HH * HH];         // W2r^T, W2s^T, W3r^T, W3s^T (k-major)

// ---------------- kNN: monolithic brute force, branchless u64-key top-16 -----
// grid (16 slices, 16 batches), block 128. One thread = one query point.
// key = (d2_bits << 32) | candidate_index  — exact (distance, index) order,
// identical to the reference's stable top_k tiebreak. Keys are unique, so the
// "replace current max" step is a predicated 16-wide select (no branches).
__global__ __launch_bounds__(128) void knn_kernel(const float* __restrict__ pts) {
    __shared__ float4 sp[NN];   // (x, y, z, |p|^2) : 32KB
    const int b = blockIdx.y;
    const float* pb = pts + (size_t)b * NN * 3;
    for (int j = threadIdx.x; j < NN; j += 128) {
        float x = pb[j * 3], y = pb[j * 3 + 1], z = pb[j * 3 + 2];
        sp[j] = make_float4(x, y, z, x * x + y * y + z * z);
    }
    __syncthreads();

    const int i = blockIdx.x * 128 + threadIdx.x;
    const float4 p = sp[i];

    unsigned long long bd[KNN];
#pragma unroll
    for (int s = 0; s < KNN; s++) bd[s] = 0xFFFFFFFFFFFFFFF0ull + s;  // distinct sentinels
    unsigned long long wv = 0xFFFFFFFFFFFFFFFFull;                     // current max (worst)

    for (int t = 0; t < NN; t++) {
        float4 q = sp[t];
        float dot = p.x * q.x + p.y * q.y + p.z * q.z;
        float d2 = p.w + q.w - 2.0f * dot;   // same formula as the reference; >= 0
        unsigned long long key =
            ((unsigned long long)__float_as_uint(d2) << 32) | (unsigned int)t;
        if (key < wv) {
            // replace the (unique) slot currently holding wv — branch-free
            const unsigned int wlo = (unsigned int)wv;
#pragma unroll
            for (int s = 0; s < KNN; s++) {
                bool hit = ((unsigned int)bd[s] == wlo);
                bd[s] = hit ? key : bd[s];
            }
            // rebuild wv: depth-4 max tree (15 u64 max ops)
            unsigned long long a0 = bd[0]  > bd[1]  ? bd[0]  : bd[1];
            unsigned long long a1 = bd[2]  > bd[3]  ? bd[2]  : bd[3];
            unsigned long long a2 = bd[4]  > bd[5]  ? bd[4]  : bd[5];
            unsigned long long a3 = bd[6]  > bd[7]  ? bd[6]  : bd[7];
            unsigned long long a4 = bd[8]  > bd[9]  ? bd[8]  : bd[9];
            unsigned long long a5 = bd[10] > bd[11] ? bd[10] : bd[11];
            unsigned long long a6 = bd[12] > bd[13] ? bd[12] : bd[13];
            unsigned long long a7 = bd[14] > bd[15] ? bd[14] : bd[15];
            unsigned long long c0 = a0 > a1 ? a0 : a1;
            unsigned long long c1 = a2 > a3 ? a2 : a3;
            unsigned long long c2 = a4 > a5 ? a4 : a5;
            unsigned long long c3 = a6 > a7 ? a6 : a7;
            unsigned long long e0 = c0 > c1 ? c0 : c1;
            unsigned long long e1 = c2 > c3 ? c2 : c3;
            wv = e0 > e1 ? e0 : e1;
        }
    }

    int* o = g_nbr + ((size_t)b * NN + i) * KNN;
#pragma unroll
    for (int s = 0; s < KNN; s++) o[s] = (int)(bd[s] & 0x7FFu);
}

// ---------------- layer 1 (input dim 3): 1 thread per point ------------------
// grid 128, block 256.
__global__ __launch_bounds__(256) void layer1_kernel(const float* __restrict__ pts,
                                                     const float* __restrict__ W1r,
                                                     const float* __restrict__ b1,
                                                     const float* __restrict__ W1s) {
    __shared__ float sWr[HH * 3], sWs[HH * 3], sb[HH];
    const int tid = threadIdx.x;
    for (int t = tid; t < HH * 3; t += 256) { sWr[t] = W1r[t]; sWs[t] = W1s[t]; }
    if (tid < 128) sb[tid] = b1[tid];
    __syncthreads();

    const int i = blockIdx.x * 256 + tid;
    const int base = (i >> 11) << 11;

    const float* xp = pts + (size_t)i * 3;
    const float x0 = xp[0], x1 = xp[1], x2 = xp[2];

    float a0 = 0.f, a1 = 0.f, a2 = 0.f;
    const int* nb = g_nbr + (size_t)i * KNN;
#pragma unroll
    for (int n = 0; n < KNN; n++) {
        int j = nb[n];
        const float* c = pts + (size_t)(base + j) * 3;
        a0 += c[0]; a1 += c[1]; a2 += c[2];
    }

    float* orow = g_h1 + (size_t)i * HH;
#pragma unroll 2
    for (int h = 0; h < HH; h += 4) {
        float4 v;
        float* vv = (float*)&v;
#pragma unroll
        for (int e = 0; e < 4; e++) {
            int hh = h + e;
            float s = sb[hh]
                    + sWr[hh * 3 + 0] * a0 + sWr[hh * 3 + 1] * a1 + sWr[hh * 3 + 2] * a2
                    + sWs[hh * 3 + 0] * x0 + sWs[hh * 3 + 1] * x1 + sWs[hh * 3 + 2] * x2;
            vv[e] = fmaxf(s, 0.0f);
        }
        *(float4*)(orow + h) = v;
    }
}

// ---------------- W transpose (k-major for coalesced GEMM staging) -----------
// grid (64, 4), block 256
__global__ __launch_bounds__(256) void transpose_kernel(const float* __restrict__ W2r,
                                                        const float* __restrict__ W2s,
                                                        const float* __restrict__ W3r,
                                                        const float* __restrict__ W3s) {
    const float* src[4] = {W2r, W2s, W3r, W3s};
    int m = blockIdx.y;
    int idx = blockIdx.x * 256 + threadIdx.x;   // 0..16383
    int k = idx >> 7, h = idx & 127;
    g_WT[m * HH * HH + k * HH + h] = src[m][h * HH + k];
}

// ---------------- layers 2/3: gather + dual GEMM (scalar FFMA, R6 exact) -----
// grid 512, block 256, 64 points per block. dyn smem 83968 B.
#define APITCH 132

template <bool RELU>
__global__ __launch_bounds__(256) void layer_kernel(const float* __restrict__ xin,
                                                    const float* __restrict__ WrT,
                                                    const float* __restrict__ bvec,
                                                    const float* __restrict__ WsT,
                                                    float* __restrict__ xout) {
    extern __shared__ float smf[];
    float* As   = smf;                       // [64][APITCH] neighbor-sum
    float* Xs   = smf + 64 * APITCH;         // [64][APITCH] self features
    float* Wr_s = smf + 2 * 64 * APITCH;     // [16][128]
    float* Ws_s = Wr_s + 16 * HH;            // [16][128]

    const int tid = threadIdx.x;
    const int P0 = blockIdx.x * 64;
    const int base = (P0 >> 11) << 11;

    // ---- gather phase: 4 threads per point, each owns 32 dims ----
    {
        const int p = tid >> 2, c = tid & 3;
        const float4* xr = (const float4*)(xin + ((size_t)P0 + p) * HH + c * 32);
        float4 acc[8];
#pragma unroll
        for (int q = 0; q < 8; q++) {
            float4 v = xr[q];
            *(float4*)(Xs + p * APITCH + c * 32 + q * 4) = v;
            acc[q] = make_float4(0.f, 0.f, 0.f, 0.f);
        }
        const int* nb = g_nbr + ((size_t)P0 + p) * KNN;
        for (int n = 0; n < KNN; n++) {
            int j = nb[n];
            const float4* ar = (const float4*)(xin + ((size_t)base + j) * HH + c * 32);
#pragma unroll
            for (int q = 0; q < 8; q++) {
                float4 v = ar[q];
                acc[q].x += v.x; acc[q].y += v.y; acc[q].z += v.z; acc[q].w += v.w;
            }
        }
#pragma unroll
        for (int q = 0; q < 8; q++)
            *(float4*)(As + p * APITCH + c * 32 + q * 4) = acc[q];
    }

    // ---- GEMM phase: warp owns 8 rows (m), lane owns 4 cols (h) ----
    const int warp = tid >> 5, lane = tid & 31;
    const int m0 = warp * 8, h0 = lane * 4;

    float acc[8][4];
#pragma unroll
    for (int i = 0; i < 8; i++)
#pragma unroll
        for (int j = 0; j < 4; j++) acc[i][j] = 0.f;

    for (int k0 = 0; k0 < HH; k0 += 16) {
        __syncthreads();   // also covers gather -> first compute
        {
            const float4* s1 = (const float4*)(WrT + (size_t)k0 * HH);
            const float4* s2 = (const float4*)(WsT + (size_t)k0 * HH);
            ((float4*)Wr_s)[tid] = s1[tid]; ((float4*)Wr_s)[tid + 256] = s1[tid + 256];
            ((float4*)Ws_s)[tid] = s2[tid]; ((float4*)Ws_s)[tid + 256] = s2[tid + 256];
        }
        __syncthreads();
#pragma unroll
        for (int kk = 0; kk < 16; kk++) {
            const int k = k0 + kk;
            float a[8], x[8];
#pragma unroll
            for (int i = 0; i < 8; i++) {
                a[i] = As[(m0 + i) * APITCH + k];   // broadcast across lanes
                x[i] = Xs[(m0 + i) * APITCH + k];
            }
            float4 wr = *(const float4*)(Wr_s + kk * HH + h0);
            float4 ws = *(const float4*)(Ws_s + kk * HH + h0);
            const float* wrf = (const float*)&wr;
            const float* wsf = (const float*)&ws;
#pragma unroll
            for (int i = 0; i < 8; i++)
#pragma unroll
                for (int j = 0; j < 4; j++)
                    acc[i][j] += a[i] * wrf[j] + x[i] * wsf[j];
        }
    }

    // ---- epilogue: + bias, optional relu, vectorized row stores ----
    const float4 bv = *(const float4*)(bvec + h0);
    const float* bf = (const float*)&bv;
#pragma unroll
    for (int i = 0; i < 8; i++) {
        float4 o; float* of = (float*)&o;
#pragma unroll
        for (int j = 0; j < 4; j++) {
            float v = acc[i][j] + bf[j];
            if (RELU) v = fmaxf(v, 0.0f);
            of[j] = v;
        }
        *(float4*)(xout + ((size_t)P0 + m0 + i) * HH + h0) = o;
    }
}

// ---------------- launch: bind inputs BY SIZE (order-robust) ----------------
extern "C" void kernel_launch(void* const* d_in, const int* in_sizes, int n_in,
                              void* d_out, int out_size) {
    const float* pts = nullptr;
    const float* w3[2]  = {nullptr, nullptr};           int n3 = 0;
    const float* wH[4]  = {nullptr, nullptr, nullptr, nullptr}; int nH = 0;
    const float* bs[3]  = {nullptr, nullptr, nullptr};  int nb_ = 0;
    for (int i = 0; i < n_in; i++) {
        const int sz = in_sizes[i];
        const float* p = (const float*)d_in[i];
        if (sz == BB * NN * 3)      pts = p;
        else if (sz == HH * 3)      { if (n3 < 2) w3[n3++] = p; }
        else if (sz == HH * HH)     { if (nH < 4) wH[nH++] = p; }
        else if (sz == HH)          { if (nb_ < 3) bs[nb_++] = p; }
    }
    const float* W1r = w3[0];  const float* W1s = w3[1];
    const float* W2r = wH[0];  const float* W2s = wH[1];
    const float* W3r = wH[2];  const float* W3s = wH[3];
    const float* b1  = bs[0];  const float* b2  = bs[1];  const float* b3 = bs[2];
    float* out = (float*)d_out;

    const int SMEM = (2 * 64 * APITCH + 2 * 16 * HH) * (int)sizeof(float);  // 83968
    cudaFuncSetAttribute(layer_kernel<true>,  cudaFuncAttributeMaxDynamicSharedMemorySize, SMEM);
    cudaFuncSetAttribute(layer_kernel<false>, cudaFuncAttributeMaxDynamicSharedMemorySize, SMEM);

    float *h1, *h2, *wt;
    cudaGetSymbolAddress((void**)&h1, g_h1);
    cudaGetSymbolAddress((void**)&h2, g_h2);
    cudaGetSymbolAddress((void**)&wt, g_WT);

    transpose_kernel<<<dim3(64, 4), 256>>>(W2r, W2s, W3r, W3s);
    knn_kernel<<<dim3(16, 16), 128>>>(pts);
    layer1_kernel<<<128, 256>>>(pts, W1r, b1, W1s);
    layer_kernel<true><<<512, 256, SMEM>>>(h1, wt, b2, wt + HH * HH, h2);
    layer_kernel<false><<<512, 256, SMEM>>>(h2, wt + 2 * HH * HH, b3, wt + 3 * HH * HH, out);
}

// round 16
// speedup vs baseline: 2.0951x; 1.2704x over previous
#include <cuda_runtime.h>
#include <cstdint>

#define BB 16
#define NN 2048
#define HH 128
#define KNN 16

// ---------------- scratch (device globals; no allocs allowed) ----------------
__device__ int   g_nbr[BB * NN * KNN];      // neighbor indices (batch-local)
__device__ float g_h1[BB * NN * HH];
__device__ float g_h2[BB * NN * HH];
__device__ float g_WT[4 * HH * HH];         // W2r^T, W2s^T, W3r^T, W3s^T (k-major)

// ---------------- kNN: monolithic brute force, branchless f32 top-16 ---------
// grid (16 slices, 16 batches), block 128. One thread = one query point.
// Slot-replace is a predicated 16-wide select on f32 distances (FSETP/FSEL),
// max rebuilt by a 15-op FMNMX tree. Strict `<` keeps the earliest index on
// boundary ties, matching the reference's stable top_k.
__global__ __launch_bounds__(128) void knn_kernel(const float* __restrict__ pts) {
    __shared__ float4 sp[NN];   // (x, y, z, |p|^2) : 32KB
    const int b = blockIdx.y;
    const float* pb = pts + (size_t)b * NN * 3;
    for (int j = threadIdx.x; j < NN; j += 128) {
        float x = pb[j * 3], y = pb[j * 3 + 1], z = pb[j * 3 + 2];
        sp[j] = make_float4(x, y, z, x * x + y * y + z * z);
    }
    __syncthreads();

    const int i = blockIdx.x * 128 + threadIdx.x;
    const float4 p = sp[i];

    float bd[KNN];
    int   bi[KNN];
#pragma unroll
    for (int s = 0; s < KNN; s++) { bd[s] = 1e30f * (1.0f + s); bi[s] = 0; }  // distinct sentinels
    float wv = 1e30f * 16.0f;   // current max (worst) of the kept set

#pragma unroll 2
    for (int t = 0; t < NN; t++) {
        float4 q = sp[t];
        float dot = p.x * q.x + p.y * q.y + p.z * q.z;
        float d2 = p.w + q.w - 2.0f * dot;   // same formula as the reference
        if (d2 < wv) {
            // replace the slot(s) currently holding wv — branch-free selects
#pragma unroll
            for (int s = 0; s < KNN; s++) {
                bool hit = (bd[s] == wv);
                bd[s] = hit ? d2 : bd[s];
                bi[s] = hit ? t  : bi[s];
            }
            // rebuild wv: depth-4 FMNMX tree
            float a0 = fmaxf(bd[0],  bd[1]);
            float a1 = fmaxf(bd[2],  bd[3]);
            float a2 = fmaxf(bd[4],  bd[5]);
            float a3 = fmaxf(bd[6],  bd[7]);
            float a4 = fmaxf(bd[8],  bd[9]);
            float a5 = fmaxf(bd[10], bd[11]);
            float a6 = fmaxf(bd[12], bd[13]);
            float a7 = fmaxf(bd[14], bd[15]);
            float c0 = fmaxf(a0, a1);
            float c1 = fmaxf(a2, a3);
            float c2 = fmaxf(a4, a5);
            float c3 = fmaxf(a6, a7);
            wv = fmaxf(fmaxf(c0, c1), fmaxf(c2, c3));
        }
    }

    int* o = g_nbr + ((size_t)b * NN + i) * KNN;
#pragma unroll
    for (int s = 0; s < KNN; s++) o[s] = bi[s];
}

// ---------------- layer 1 (input dim 3): 1 thread per point ------------------
// grid 128, block 256.
__global__ __launch_bounds__(256) void layer1_kernel(const float* __restrict__ pts,
                                                     const float* __restrict__ W1r,
                                                     const float* __restrict__ b1,
                                                     const float* __restrict__ W1s) {
    __shared__ float sWr[HH * 3], sWs[HH * 3], sb[HH];
    const int tid = threadIdx.x;
    for (int t = tid; t < HH * 3; t += 256) { sWr[t] = W1r[t]; sWs[t] = W1s[t]; }
    if (tid < 128) sb[tid] = b1[tid];
    __syncthreads();

    const int i = blockIdx.x * 256 + tid;
    const int base = (i >> 11) << 11;

    const float* xp = pts + (size_t)i * 3;
    const float x0 = xp[0], x1 = xp[1], x2 = xp[2];

    float a0 = 0.f, a1 = 0.f, a2 = 0.f;
    const int* nb = g_nbr + (size_t)i * KNN;
#pragma unroll
    for (int n = 0; n < KNN; n++) {
        int j = nb[n];
        const float* c = pts + (size_t)(base + j) * 3;
        a0 += c[0]; a1 += c[1]; a2 += c[2];
    }

    float* orow = g_h1 + (size_t)i * HH;
#pragma unroll 2
    for (int h = 0; h < HH; h += 4) {
        float4 v;
        float* vv = (float*)&v;
#pragma unroll
        for (int e = 0; e < 4; e++) {
            int hh = h + e;
            float s = sb[hh]
                    + sWr[hh * 3 + 0] * a0 + sWr[hh * 3 + 1] * a1 + sWr[hh * 3 + 2] * a2
                    + sWs[hh * 3 + 0] * x0 + sWs[hh * 3 + 1] * x1 + sWs[hh * 3 + 2] * x2;
            vv[e] = fmaxf(s, 0.0f);
        }
        *(float4*)(orow + h) = v;
    }
}

// ---------------- W transpose (k-major for coalesced GEMM staging) -----------
// grid (64, 4), block 256
__global__ __launch_bounds__(256) void transpose_kernel(const float* __restrict__ W2r,
                                                        const float* __restrict__ W2s,
                                                        const float* __restrict__ W3r,
                                                        const float* __restrict__ W3s) {
    const float* src[4] = {W2r, W2s, W3r, W3s};
    int m = blockIdx.y;
    int idx = blockIdx.x * 256 + threadIdx.x;   // 0..16383
    int k = idx >> 7, h = idx & 127;
    g_WT[m * HH * HH + k * HH + h] = src[m][h * HH + k];
}

// ---------------- layers 2/3: gather + dual GEMM (scalar FFMA, k-major) ------
// grid 512, block 256, 64 points per block. dyn smem 86016 B.
// As/Xs are k-major [128][KP] (KP=68 keeps 16B alignment for the 8-row reads),
// so the 8 activation rows a warp needs per k are 2 broadcast LDS.128 each.
#define KP 68

template <bool RELU>
__global__ __launch_bounds__(256) void layer_kernel(const float* __restrict__ xin,
                                                    const float* __restrict__ WrT,
                                                    const float* __restrict__ bvec,
                                                    const float* __restrict__ WsT,
                                                    float* __restrict__ xout) {
    extern __shared__ float smf[];
    float* As   = smf;                     // [128][KP] neighbor-sum, k-major
    float* Xs   = smf + 128 * KP;          // [128][KP] self features, k-major
    float* Wr_s = smf + 2 * 128 * KP;      // [16][128]
    float* Ws_s = Wr_s + 16 * HH;          // [16][128]

    const int tid = threadIdx.x;
    const int P0 = blockIdx.x * 64;
    const int base = (P0 >> 11) << 11;

    // ---- gather phase: 4 threads per point, each owns 32 dims ----
    {
        const int p = tid >> 2, c = tid & 3;
        const float4* xr = (const float4*)(xin + ((size_t)P0 + p) * HH + c * 32);
        float4 acc[8];
#pragma unroll
        for (int q = 0; q < 8; q++) {
            float4 v = xr[q];
            const int k = c * 32 + q * 4;
            Xs[(k + 0) * KP + p] = v.x;
            Xs[(k + 1) * KP + p] = v.y;
            Xs[(k + 2) * KP + p] = v.z;
            Xs[(k + 3) * KP + p] = v.w;
            acc[q] = make_float4(0.f, 0.f, 0.f, 0.f);
        }
        const int* nb = g_nbr + ((size_t)P0 + p) * KNN;
        for (int n = 0; n < KNN; n++) {
            int j = nb[n];
            const float4* ar = (const float4*)(xin + ((size_t)base + j) * HH + c * 32);
#pragma unroll
            for (int q = 0; q < 8; q++) {
                float4 v = ar[q];
                acc[q].x += v.x; acc[q].y += v.y; acc[q].z += v.z; acc[q].w += v.w;
            }
        }
#pragma unroll
        for (int q = 0; q < 8; q++) {
            const int k = c * 32 + q * 4;
            As[(k + 0) * KP + p] = acc[q].x;
            As[(k + 1) * KP + p] = acc[q].y;
            As[(k + 2) * KP + p] = acc[q].z;
            As[(k + 3) * KP + p] = acc[q].w;
        }
    }

    // ---- GEMM phase: warp owns 8 rows (m), lane owns 4 cols (h) ----
    const int warp = tid >> 5, lane = tid & 31;
    const int m0 = warp * 8, h0 = lane * 4;

    float acc[8][4];
#pragma unroll
    for (int i = 0; i < 8; i++)
#pragma unroll
        for (int j = 0; j < 4; j++) acc[i][j] = 0.f;

    for (int k0 = 0; k0 < HH; k0 += 16) {
        __syncthreads();   // also covers gather -> first compute
        {
            const float4* s1 = (const float4*)(WrT + (size_t)k0 * HH);
            const float4* s2 = (const float4*)(WsT + (size_t)k0 * HH);
            ((float4*)Wr_s)[tid] = s1[tid]; ((float4*)Wr_s)[tid + 256] = s1[tid + 256];
            ((float4*)Ws_s)[tid] = s2[tid]; ((float4*)Ws_s)[tid + 256] = s2[tid + 256];
        }
        __syncthreads();
#pragma unroll
        for (int kk = 0; kk < 16; kk++) {
            const int k = k0 + kk;
            // 8 activation rows = 2 broadcast LDS.128 each for As and Xs
            const float4* ap = (const float4*)(As + k * KP + m0);
            const float4* xp = (const float4*)(Xs + k * KP + m0);
            float4 av0 = ap[0], av1 = ap[1];
            float4 xv0 = xp[0], xv1 = xp[1];
            float a[8] = {av0.x, av0.y, av0.z, av0.w, av1.x, av1.y, av1.z, av1.w};
            float x[8] = {xv0.x, xv0.y, xv0.z, xv0.w, xv1.x, xv1.y, xv1.z, xv1.w};

            float4 wr = *(const float4*)(Wr_s + kk * HH + h0);
            float4 ws = *(const float4*)(Ws_s + kk * HH + h0);
            const float* wrf = (const float*)&wr;
            const float* wsf = (const float*)&ws;
#pragma unroll
            for (int i = 0; i < 8; i++)
#pragma unroll
                for (int j = 0; j < 4; j++)
                    acc[i][j] += a[i] * wrf[j] + x[i] * wsf[j];
        }
    }

    // ---- epilogue: + bias, optional relu, vectorized row stores ----
    const float4 bv = *(const float4*)(bvec + h0);
    const float* bf = (const float*)&bv;
#pragma unroll
    for (int i = 0; i < 8; i++) {
        float4 o; float* of = (float*)&o;
#pragma unroll
        for (int j = 0; j < 4; j++) {
            float v = acc[i][j] + bf[j];
            if (RELU) v = fmaxf(v, 0.0f);
            of[j] = v;
        }
        *(float4*)(xout + ((size_t)P0 + m0 + i) * HH + h0) = o;
    }
}

// ---------------- launch: bind inputs BY SIZE (order-robust) ----------------
extern "C" void kernel_launch(void* const* d_in, const int* in_sizes, int n_in,
                              void* d_out, int out_size) {
    const float* pts = nullptr;
    const float* w3[2]  = {nullptr, nullptr};           int n3 = 0;
    const float* wH[4]  = {nullptr, nullptr, nullptr, nullptr}; int nH = 0;
    const float* bs[3]  = {nullptr, nullptr, nullptr};  int nb_ = 0;
    for (int i = 0; i < n_in; i++) {
        const int sz = in_sizes[i];
        const float* p = (const float*)d_in[i];
        if (sz == BB * NN * 3)      pts = p;
        else if (sz == HH * 3)      { if (n3 < 2) w3[n3++] = p; }
        else if (sz == HH * HH)     { if (nH < 4) wH[nH++] = p; }
        else if (sz == HH)          { if (nb_ < 3) bs[nb_++] = p; }
    }
    const float* W1r = w3[0];  const float* W1s = w3[1];
    const float* W2r = wH[0];  const float* W2s = wH[1];
    const float* W3r = wH[2];  const float* W3s = wH[3];
    const float* b1  = bs[0];  const float* b2  = bs[1];  const float* b3 = bs[2];
    float* out = (float*)d_out;

    const int SMEM = (2 * 128 * KP + 2 * 16 * HH) * (int)sizeof(float);  // 86016
    cudaFuncSetAttribute(layer_kernel<true>,  cudaFuncAttributeMaxDynamicSharedMemorySize, SMEM);
    cudaFuncSetAttribute(layer_kernel<false>, cudaFuncAttributeMaxDynamicSharedMemorySize, SMEM);

    float *h1, *h2, *wt;
    cudaGetSymbolAddress((void**)&h1, g_h1);
    cudaGetSymbolAddress((void**)&h2, g_h2);
    cudaGetSymbolAddress((void**)&wt, g_WT);

    transpose_kernel<<<dim3(64, 4), 256>>>(W2r, W2s, W3r, W3s);
    knn_kernel<<<dim3(16, 16), 128>>>(pts);
    layer1_kernel<<<128, 256>>>(pts, W1r, b1, W1s);
    layer_kernel<true><<<512, 256, SMEM>>>(h1, wt, b2, wt + HH * HH, h2);
    layer_kernel<false><<<512, 256, SMEM>>>(h2, wt + 2 * HH * HH, b3, wt + 3 * HH * HH, out);
}